// round 4
// baseline (speedup 1.0000x reference)
#include <cuda_runtime.h>

#define B_  2
#define L_  2048
#define D_  1024
#define H_  16
#define DH_ 64
#define SCALE_ 0.125f

// ---------------- scratch (no allocations allowed) ----------------
__device__ float g_Q[B_ * H_ * DH_ * L_];   // [B,H,DH,L] (dh-major for transposed tile loads)
__device__ float g_K[B_ * H_ * DH_ * L_];   // [B,H,DH,L]
__device__ float g_V[B_ * H_ * L_ * DH_];   // [B,H,L,DH]
__device__ float g_O[B_ * L_ * D_];         // [B,L,D] attention output (GEMM2 input)
__device__ int   g_mask[B_ * L_];
__device__ int   g_is_i32;

// ---------------- mask dtype detect + convert ----------------
// The harness may hand the bool mask as 1-byte bools or as int32 (or float32).
// Scan the first n_bytes/4 words: any value > 1 means the buffer is packed
// bytes (bool). int32/float32 masks have only 0 words in that range for this
// pattern. conv then treats "nonzero word" as masked (covers i32 and f32).
__global__ void k_reset() {
    if (threadIdx.x == 0 && blockIdx.x == 0) g_is_i32 = 1;
}
__global__ void k_detect(const unsigned int* __restrict__ p, int n4) {
    int i = blockIdx.x * blockDim.x + threadIdx.x;
    for (; i < n4; i += gridDim.x * blockDim.x) {
        if (p[i] > 1u) atomicExch(&g_is_i32, 0);
    }
}
__global__ void k_conv(const void* __restrict__ raw, int n) {
    int i = blockIdx.x * blockDim.x + threadIdx.x;
    if (i < n) {
        int v;
        if (g_is_i32) v = (((const int*)raw)[i] != 0) ? 1 : 0;
        else          v = (((const unsigned char*)raw)[i] != 0) ? 1 : 0;
        g_mask[i] = v;
    }
}

// ---------------- 128x128x8 fp32 SGEMM ----------------
// mode 0: C[m,n] = acc + bias[n]
// mode 1: scatter into g_Q/g_K ([B,H,DH,L]) and g_V ([B,H,L,DH])
__global__ void __launch_bounds__(256) sgemm128(
    const float* __restrict__ A, const float* __restrict__ Bw,
    const float* __restrict__ bias, float* __restrict__ C,
    int M, int N, int K, int mode)
{
    __shared__ float As[8][128];
    __shared__ float Bs[8][128];

    const int tid = threadIdx.x;
    const int tx = tid & 15, ty = tid >> 4;
    const int bm = blockIdx.y * 128, bn = blockIdx.x * 128;

    const int arow = tid >> 1;
    const int acol = (tid & 1) * 4;
    const int brow = tid >> 5;
    const int bcol = (tid & 31) * 4;

    const float* Ap = A + (size_t)(bm + arow) * K + acol;
    const float* Bp = Bw + (size_t)brow * N + bn + bcol;

    float acc[8][8];
#pragma unroll
    for (int i = 0; i < 8; i++)
#pragma unroll
        for (int j = 0; j < 8; j++) acc[i][j] = 0.0f;

    for (int kt = 0; kt < K; kt += 8) {
        float4 av = *(const float4*)Ap;
        float4 bv = *(const float4*)Bp;
        Ap += 8;
        Bp += (size_t)8 * N;

        As[acol + 0][arow] = av.x;
        As[acol + 1][arow] = av.y;
        As[acol + 2][arow] = av.z;
        As[acol + 3][arow] = av.w;
        *(float4*)&Bs[brow][bcol] = bv;
        __syncthreads();

#pragma unroll
        for (int k = 0; k < 8; k++) {
            float a[8], b[8];
            *(float4*)(a)     = *(float4*)&As[k][ty * 4];
            *(float4*)(a + 4) = *(float4*)&As[k][64 + ty * 4];
            *(float4*)(b)     = *(float4*)&Bs[k][tx * 4];
            *(float4*)(b + 4) = *(float4*)&Bs[k][64 + tx * 4];
#pragma unroll
            for (int i = 0; i < 8; i++)
#pragma unroll
                for (int j = 0; j < 8; j++) acc[i][j] += a[i] * b[j];
        }
        __syncthreads();
    }

#pragma unroll
    for (int i = 0; i < 8; i++) {
        int r = bm + ((i < 4) ? (ty * 4 + i) : (64 + ty * 4 + i - 4));
#pragma unroll
        for (int j = 0; j < 8; j++) {
            int cn = bn + ((j < 4) ? (tx * 4 + j) : (64 + tx * 4 + j - 4));
            float v = acc[i][j] + bias[cn];
            if (mode == 0) {
                C[(size_t)r * N + cn] = v;
            } else {
                int which = cn >> 10;
                int dd = cn & 1023;
                int hh = dd >> 6, dh = dd & 63;
                int bb = r >> 11, ll = r & 2047;
                if (which == 0)
                    g_Q[(((size_t)(bb * H_ + hh)) * DH_ + dh) * L_ + ll] = v;
                else if (which == 1)
                    g_K[(((size_t)(bb * H_ + hh)) * DH_ + dh) * L_ + ll] = v;
                else
                    g_V[(((size_t)(bb * H_ + hh)) * L_ + ll) * DH_ + dh] = v;
            }
        }
    }
}

// ---------------- flash attention (fp32), 64-row q tiles ----------------
// grid: (L/64, H, B), 256 threads. smem = 3 * 16KB = 48KB exactly.
__global__ void __launch_bounds__(256) attn_kernel()
{
    const int qt = blockIdx.x, h = blockIdx.y, b = blockIdx.z;
    __shared__ float Qts[64 * 64];  // [d][qrow]
    __shared__ float KP[64 * 64];   // Kts [d][key] during S; P [qrow][key] during PV
    __shared__ float Vs[64 * 64];   // [key][d]

    const int tid = threadIdx.x;
    const int tx = tid & 15, ty = tid >> 4;

    const float* Qg = g_Q + ((size_t)(b * H_ + h)) * DH_ * L_ + qt * 64;
    const float* Kg = g_K + ((size_t)(b * H_ + h)) * DH_ * L_;
    const float* Vg = g_V + ((size_t)(b * H_ + h)) * L_ * DH_;
    const int* mk = g_mask + b * L_;

    // Q tile, transposed-in-global so load+store are both coalesced/conflict-free
#pragma unroll
    for (int rep = 0; rep < 4; rep++) {
        int lin = tid + rep * 256;
        int d = lin >> 4, j4 = (lin & 15) * 4;
        *(float4*)&Qts[d * 64 + j4] = *(const float4*)(Qg + (size_t)d * L_ + j4);
    }

    float m_i[4], l_i[4], o[4][4];
#pragma unroll
    for (int ii = 0; ii < 4; ii++) {
        m_i[ii] = -1e30f;
        l_i[ii] = 0.0f;
#pragma unroll
        for (int jj = 0; jj < 4; jj++) o[ii][jj] = 0.0f;
    }

    for (int kt0 = 0; kt0 < L_; kt0 += 64) {
        __syncthreads();  // previous PV reads of KP/Vs done
#pragma unroll
        for (int rep = 0; rep < 4; rep++) {
            int lin = tid + rep * 256;
            int d = lin >> 4, j4 = (lin & 15) * 4;
            *(float4*)&KP[d * 64 + j4] = *(const float4*)(Kg + (size_t)d * L_ + kt0 + j4);
        }
#pragma unroll
        for (int rep = 0; rep < 4; rep++) {
            int lin = tid + rep * 256;
            int j = lin >> 4, d4 = (lin & 15) * 4;
            *(float4*)&Vs[j * 64 + d4] = *(const float4*)(Vg + (size_t)(kt0 + j) * DH_ + d4);
        }
        __syncthreads();

        // S = Q K^T, outer-product form
        float s[4][4];
#pragma unroll
        for (int ii = 0; ii < 4; ii++)
#pragma unroll
            for (int jj = 0; jj < 4; jj++) s[ii][jj] = 0.0f;

#pragma unroll
        for (int d = 0; d < 64; d++) {
            float4 q = *(float4*)&Qts[d * 64 + ty * 4];
            float4 k = *(float4*)&KP[d * 64 + tx * 4];
            s[0][0] += q.x * k.x; s[0][1] += q.x * k.y; s[0][2] += q.x * k.z; s[0][3] += q.x * k.w;
            s[1][0] += q.y * k.x; s[1][1] += q.y * k.y; s[1][2] += q.y * k.z; s[1][3] += q.y * k.w;
            s[2][0] += q.z * k.x; s[2][1] += q.z * k.y; s[2][2] += q.z * k.z; s[2][3] += q.z * k.w;
            s[3][0] += q.w * k.x; s[3][1] += q.w * k.y; s[3][2] += q.w * k.z; s[3][3] += q.w * k.w;
        }

        // scale + key-padding mask
        float mb[4];
#pragma unroll
        for (int jj = 0; jj < 4; jj++)
            mb[jj] = mk[kt0 + tx * 4 + jj] ? -1e30f : 0.0f;
#pragma unroll
        for (int ii = 0; ii < 4; ii++)
#pragma unroll
            for (int jj = 0; jj < 4; jj++)
                s[ii][jj] = s[ii][jj] * SCALE_ + mb[jj];

        // online softmax (rows owned by a 16-lane group; reduce over tx)
        float p[4][4];
#pragma unroll
        for (int ii = 0; ii < 4; ii++) {
            float mx = fmaxf(fmaxf(s[ii][0], s[ii][1]), fmaxf(s[ii][2], s[ii][3]));
            mx = fmaxf(mx, __shfl_xor_sync(0xffffffffu, mx, 8));
            mx = fmaxf(mx, __shfl_xor_sync(0xffffffffu, mx, 4));
            mx = fmaxf(mx, __shfl_xor_sync(0xffffffffu, mx, 2));
            mx = fmaxf(mx, __shfl_xor_sync(0xffffffffu, mx, 1));
            float mnew = fmaxf(m_i[ii], mx);
            float alpha = __expf(m_i[ii] - mnew);
            m_i[ii] = mnew;
            float rs = 0.0f;
#pragma unroll
            for (int jj = 0; jj < 4; jj++) {
                p[ii][jj] = __expf(s[ii][jj] - mnew);
                rs += p[ii][jj];
            }
            rs += __shfl_xor_sync(0xffffffffu, rs, 8);
            rs += __shfl_xor_sync(0xffffffffu, rs, 4);
            rs += __shfl_xor_sync(0xffffffffu, rs, 2);
            rs += __shfl_xor_sync(0xffffffffu, rs, 1);
            l_i[ii] = l_i[ii] * alpha + rs;
#pragma unroll
            for (int jj = 0; jj < 4; jj++) o[ii][jj] *= alpha;
        }

        __syncthreads();  // all done reading KP as K
#pragma unroll
        for (int ii = 0; ii < 4; ii++)
#pragma unroll
            for (int jj = 0; jj < 4; jj++)
                KP[(ty * 4 + ii) * 64 + tx * 4 + jj] = p[ii][jj];
        __syncthreads();

        // O += P V
#pragma unroll
        for (int j = 0; j < 64; j++) {
            float4 v = *(float4*)&Vs[j * 64 + tx * 4];
            float p0 = KP[(ty * 4 + 0) * 64 + j];
            float p1 = KP[(ty * 4 + 1) * 64 + j];
            float p2 = KP[(ty * 4 + 2) * 64 + j];
            float p3 = KP[(ty * 4 + 3) * 64 + j];
            o[0][0] += p0 * v.x; o[0][1] += p0 * v.y; o[0][2] += p0 * v.z; o[0][3] += p0 * v.w;
            o[1][0] += p1 * v.x; o[1][1] += p1 * v.y; o[1][2] += p1 * v.z; o[1][3] += p1 * v.w;
            o[2][0] += p2 * v.x; o[2][1] += p2 * v.y; o[2][2] += p2 * v.z; o[2][3] += p2 * v.w;
            o[3][0] += p3 * v.x; o[3][1] += p3 * v.y; o[3][2] += p3 * v.z; o[3][3] += p3 * v.w;
        }
    }

#pragma unroll
    for (int ii = 0; ii < 4; ii++) {
        float inv = 1.0f / l_i[ii];
        float4 r;
        r.x = o[ii][0] * inv; r.y = o[ii][1] * inv;
        r.z = o[ii][2] * inv; r.w = o[ii][3] * inv;
        size_t addr = ((size_t)(b * L_ + qt * 64 + ty * 4 + ii)) * D_ + h * DH_ + tx * 4;
        *(float4*)(g_O + addr) = r;
    }
}

// ---------------- launch ----------------
extern "C" void kernel_launch(void* const* d_in, const int* in_sizes, int n_in,
                              void* d_out, int out_size)
{
    const float* x     = (const float*)d_in[0];
    const float* w_qkv = (const float*)d_in[1];
    const float* b_qkv = (const float*)d_in[2];
    const float* w_out = (const float*)d_in[3];
    const float* b_out = (const float*)d_in[4];
    const void*  mask  = d_in[5];

    float* Optr = nullptr;
    cudaGetSymbolAddress((void**)&Optr, g_O);

    k_reset<<<1, 32>>>();
    k_detect<<<4, 256>>>((const unsigned int*)mask, (B_ * L_) / 4);
    k_conv<<<(B_ * L_ + 255) / 256, 256>>>(mask, B_ * L_);

    // QKV projection + scatter
    sgemm128<<<dim3(3 * D_ / 128, B_ * L_ / 128), 256>>>(
        x, w_qkv, b_qkv, nullptr, B_ * L_, 3 * D_, D_, 1);

    // attention
    attn_kernel<<<dim3(L_ / 64, H_, B_), 256>>>();

    // output projection
    sgemm128<<<dim3(D_ / 128, B_ * L_ / 128), 256>>>(
        Optr, w_out, b_out, (float*)d_out, B_ * L_, D_, D_, 0);
}

// round 9
// speedup vs baseline: 1.4391x; 1.4391x over previous
#include <cuda_runtime.h>
#include <cuda_bf16.h>
#include <cstdint>

#define B_  2
#define L_  2048
#define D_  1024
#define H_  16
#define DH_ 64
#define M_  (B_ * L_)      /* 4096 rows */
#define K_  D_             /* 1024 reduction */
#define SCALE_ 0.125f

// ---------------- scratch (no allocations allowed) ----------------
__device__ float g_Q[B_ * H_ * DH_ * L_];   // [B,H,DH,L]
__device__ float g_K[B_ * H_ * DH_ * L_];   // [B,H,DH,L]
__device__ float g_V[B_ * H_ * L_ * DH_];   // [B,H,L,DH]
__device__ float g_O[B_ * L_ * D_];         // [B,L,D]
__device__ int   g_mask[B_ * L_];
__device__ int   g_is_i32;

// bf16 split operands
__device__ __nv_bfloat16 g_Xh[M_ * K_],      g_Xl[M_ * K_];       // x [M,K]
__device__ __nv_bfloat16 g_Wqh[3 * D_ * K_], g_Wql[3 * D_ * K_];  // w_qkv^T [3072,K]
__device__ __nv_bfloat16 g_Woh[D_ * K_],     g_Wol[D_ * K_];      // w_out^T [1024,K]
__device__ __nv_bfloat16 g_Oh[M_ * K_],      g_Ol[M_ * K_];       // attn out [M,K]

// ---------------- mask dtype detect + convert ----------------
__global__ void k_reset() {
    if (threadIdx.x == 0 && blockIdx.x == 0) g_is_i32 = 1;
}
__global__ void k_detect(const unsigned int* __restrict__ p, int n4) {
    int i = blockIdx.x * blockDim.x + threadIdx.x;
    for (; i < n4; i += gridDim.x * blockDim.x) {
        if (p[i] > 1u) atomicExch(&g_is_i32, 0);
    }
}
__global__ void k_conv(const void* __restrict__ raw, int n) {
    int i = blockIdx.x * blockDim.x + threadIdx.x;
    if (i < n) {
        int v;
        if (g_is_i32) v = (((const int*)raw)[i] != 0) ? 1 : 0;
        else          v = (((const unsigned char*)raw)[i] != 0) ? 1 : 0;
        g_mask[i] = v;
    }
}

// ---------------- fp32 -> bf16 hi/lo split ----------------
__global__ void k_split(const float* __restrict__ in,
                        __nv_bfloat16* __restrict__ hi,
                        __nv_bfloat16* __restrict__ lo, int n4)
{
    int i = blockIdx.x * blockDim.x + threadIdx.x;
    if (i >= n4) return;
    float4 v = ((const float4*)in)[i];
    __nv_bfloat16 h0 = __float2bfloat16(v.x);
    __nv_bfloat16 h1 = __float2bfloat16(v.y);
    __nv_bfloat16 h2 = __float2bfloat16(v.z);
    __nv_bfloat16 h3 = __float2bfloat16(v.w);
    __nv_bfloat162* hp = (__nv_bfloat162*)hi;
    __nv_bfloat162* lp = (__nv_bfloat162*)lo;
    hp[2 * i + 0] = __nv_bfloat162(h0, h1);
    hp[2 * i + 1] = __nv_bfloat162(h2, h3);
    lp[2 * i + 0] = __nv_bfloat162(__float2bfloat16(v.x - __bfloat162float(h0)),
                                   __float2bfloat16(v.y - __bfloat162float(h1)));
    lp[2 * i + 1] = __nv_bfloat162(__float2bfloat16(v.z - __bfloat162float(h2)),
                                   __float2bfloat16(v.w - __bfloat162float(h3)));
}

// ---------------- fp32 [K,N] -> bf16 hi/lo [N,K] (split + transpose) --------
__global__ void k_splitT(const float* __restrict__ w,
                         __nv_bfloat16* __restrict__ hi,
                         __nv_bfloat16* __restrict__ lo, int N)
{
    __shared__ float t[32][33];
    int n0 = blockIdx.x * 32, k0 = blockIdx.y * 32;
    int tx = threadIdx.x, ty = threadIdx.y;   // 32 x 8
#pragma unroll
    for (int i = 0; i < 32; i += 8)
        t[ty + i][tx] = w[(size_t)(k0 + ty + i) * N + n0 + tx];
    __syncthreads();
#pragma unroll
    for (int i = 0; i < 32; i += 8) {
        float v = t[tx][ty + i];
        size_t o = (size_t)(n0 + ty + i) * K_ + k0 + tx;
        __nv_bfloat16 h = __float2bfloat16(v);
        hi[o] = h;
        lo[o] = __float2bfloat16(v - __bfloat162float(h));
    }
}

// ---------------- warp-mma helpers (family-safe PTX, no tcgen05) ------------
__device__ __forceinline__ uint32_t smem_u32(const void* p) {
    uint32_t a;
    asm("{ .reg .u64 t; cvta.to.shared.u64 t, %1; cvt.u32.u64 %0, t; }"
        : "=r"(a) : "l"(p));
    return a;
}
__device__ __forceinline__ void ldm_x4(uint32_t* r, uint32_t addr) {
    asm volatile("ldmatrix.sync.aligned.m8n8.x4.shared.b16 {%0,%1,%2,%3}, [%4];"
                 : "=r"(r[0]), "=r"(r[1]), "=r"(r[2]), "=r"(r[3]) : "r"(addr));
}
__device__ __forceinline__ void mma_bf16(float* d, const uint32_t* a, const uint32_t* b) {
    asm volatile(
        "mma.sync.aligned.m16n8k16.row.col.f32.bf16.bf16.f32 "
        "{%0,%1,%2,%3}, {%4,%5,%6,%7}, {%8,%9}, {%0,%1,%2,%3};"
        : "+f"(d[0]), "+f"(d[1]), "+f"(d[2]), "+f"(d[3])
        : "r"(a[0]), "r"(a[1]), "r"(a[2]), "r"(a[3]), "r"(b[0]), "r"(b[1]));
}
__device__ __forceinline__ void cpasync16(uint32_t saddr, const void* g) {
    asm volatile("cp.async.cg.shared.global [%0], [%1], 16;" :: "r"(saddr), "l"(g));
}
__device__ __forceinline__ void cp_commit() {
    asm volatile("cp.async.commit_group;" ::: "memory");
}
__device__ __forceinline__ void cp_wait0() {
    asm volatile("cp.async.wait_group 0;" ::: "memory");
}

// ---------------- bf16-split GEMM via mma.sync: C = A * B^T + bias ----------
// A[M,K] row-major (hi+lo), B[N,K] row-major (hi+lo). CTA 128x128, K-chunk 64,
// double-buffered cp.async. mode 0: write C+bias. mode 1: scatter Q/K/V.
#define TILE_B   16384                 /* one 128x64 bf16 tile */
#define BUF_B    (4 * TILE_B)          /* Ah|Al|Bh|Bl          */
#define GEMM_SMEM (2 * BUF_B)          /* 131072               */

__global__ void __launch_bounds__(256, 1) gemm_mma(
    const __nv_bfloat16* __restrict__ Ah, const __nv_bfloat16* __restrict__ Al,
    const __nv_bfloat16* __restrict__ Bh, const __nv_bfloat16* __restrict__ Bl,
    const float* __restrict__ bias, float* __restrict__ C, int N, int mode)
{
    extern __shared__ __align__(1024) char smem[];
    const uint32_t sb = smem_u32(smem);
    const int tid = threadIdx.x, wid = tid >> 5, lid = tid & 31;
    const int warp_m = wid & 3, warp_n = wid >> 2;      // 4 x 2 warps
    const int bm = blockIdx.y * 128, bn = blockIdx.x * 128;

    const __nv_bfloat16* srcs[4] = { Ah, Al, Bh, Bl };
    const int rbs[4] = { bm, bm, bn, bn };

    // per-thread gmem/smem offsets for cooperative loads (4 x 16B per tile)
    int lrow[4], lu[4]; uint32_t lso[4];
#pragma unroll
    for (int i = 0; i < 4; i++) {
        int un = tid + i * 256;            // 0..1023
        lrow[i] = un >> 3; lu[i] = un & 7;
        uint32_t off = lrow[i] * 128 + lu[i] * 16;
        off ^= (off >> 3) & 0x70;          // SW128 swizzle
        lso[i] = off;
    }

    auto load_chunk = [&](int c) {
        const int kt = c * 64;
        const uint32_t bo = sb + (c & 1) * BUF_B;
#pragma unroll
        for (int s = 0; s < 4; s++) {
            const __nv_bfloat16* src = srcs[s];
            const int rb = rbs[s];
#pragma unroll
            for (int i = 0; i < 4; i++)
                cpasync16(bo + s * TILE_B + lso[i],
                          src + (size_t)(rb + lrow[i]) * K_ + kt + lu[i] * 8);
        }
        cp_commit();
    };

    float acc[2][8][4];
#pragma unroll
    for (int i = 0; i < 2; i++)
#pragma unroll
        for (int j = 0; j < 8; j++)
#pragma unroll
            for (int e = 0; e < 4; e++) acc[i][j][e] = 0.0f;

    // ldmatrix lane-address components
    const int q = lid >> 3, rsub = lid & 7;
    const int a_radd = (q & 1) * 8, a_kadd = (q >> 1) * 16;   // A: m16k16 x4
    const int b_radd = (q >> 1) * 8, b_kadd = (q & 1) * 16;   // B: two n8k16 per x4

    load_chunk(0);

    for (int c = 0; c < 16; c++) {
        cp_wait0();
        __syncthreads();
        if (c + 1 < 16) load_chunk(c + 1);

        const uint32_t bo = sb + (c & 1) * BUF_B;
        const uint32_t sAh = bo, sAl = bo + TILE_B;
        const uint32_t sBh = bo + 2 * TILE_B, sBl = bo + 3 * TILE_B;

#pragma unroll
        for (int ks = 0; ks < 4; ks++) {
            uint32_t ah[2][4], al[2][4];
#pragma unroll
            for (int i = 0; i < 2; i++) {
                uint32_t off = (uint32_t)(warp_m * 32 + i * 16 + a_radd + rsub) * 128
                             + ks * 32 + a_kadd;
                off ^= (off >> 3) & 0x70;
                ldm_x4(ah[i], sAh + off);
                ldm_x4(al[i], sAl + off);
            }
#pragma unroll
            for (int nb = 0; nb < 4; nb++) {   // 16 cols per iter
                uint32_t bh[4], bl[4];
                uint32_t off = (uint32_t)(warp_n * 64 + nb * 16 + b_radd + rsub) * 128
                             + ks * 32 + b_kadd;
                off ^= (off >> 3) & 0x70;
                ldm_x4(bh, sBh + off);
                ldm_x4(bl, sBl + off);
#pragma unroll
                for (int i = 0; i < 2; i++)
#pragma unroll
                    for (int t = 0; t < 2; t++) {
                        float* d = acc[i][nb * 2 + t];
                        mma_bf16(d, ah[i], bh + t * 2);
                        mma_bf16(d, ah[i], bl + t * 2);
                        mma_bf16(d, al[i], bh + t * 2);
                    }
            }
        }
        __syncthreads();
    }

    // epilogue: fragment (m16n8 f32): d0=(g, t2) d1=(g, t2+1) d2=(g+8, t2) d3=(g+8, t2+1)
    const int g = lid >> 2, t2 = (lid & 3) * 2;
#pragma unroll
    for (int i = 0; i < 2; i++) {
        const int r0 = bm + warp_m * 32 + i * 16 + g;
#pragma unroll
        for (int j = 0; j < 8; j++) {
            const int cn = bn + warp_n * 64 + j * 8 + t2;
#pragma unroll
            for (int e = 0; e < 4; e++) {
                const int r = r0 + (e >> 1) * 8;
                const int n = cn + (e & 1);
                const float v = acc[i][j][e] + bias[n];
                if (mode == 0) {
                    C[(size_t)r * N + n] = v;
                } else {
                    const int which = n >> 10;
                    const int dd = n & 1023;
                    const int hh = dd >> 6, dh = dd & 63;
                    const int bb = r >> 11, ll = r & 2047;
                    if (which == 0)
                        g_Q[(((size_t)(bb * H_ + hh)) * DH_ + dh) * L_ + ll] = v;
                    else if (which == 1)
                        g_K[(((size_t)(bb * H_ + hh)) * DH_ + dh) * L_ + ll] = v;
                    else
                        g_V[(((size_t)(bb * H_ + hh)) * L_ + ll) * DH_ + dh] = v;
                }
            }
        }
    }
}

// ---------------- flash attention (fp32), 64-row q tiles ----------------
__global__ void __launch_bounds__(256) attn_kernel()
{
    const int qt = blockIdx.x, h = blockIdx.y, b = blockIdx.z;
    __shared__ float Qts[64 * 64];
    __shared__ float KP[64 * 64];
    __shared__ float Vs[64 * 64];

    const int tid = threadIdx.x;
    const int tx = tid & 15, ty = tid >> 4;

    const float* Qg = g_Q + ((size_t)(b * H_ + h)) * DH_ * L_ + qt * 64;
    const float* Kg = g_K + ((size_t)(b * H_ + h)) * DH_ * L_;
    const float* Vg = g_V + ((size_t)(b * H_ + h)) * L_ * DH_;
    const int* mk = g_mask + b * L_;

#pragma unroll
    for (int rep = 0; rep < 4; rep++) {
        int lin = tid + rep * 256;
        int d = lin >> 4, j4 = (lin & 15) * 4;
        *(float4*)&Qts[d * 64 + j4] = *(const float4*)(Qg + (size_t)d * L_ + j4);
    }

    float m_i[4], l_i[4], o[4][4];
#pragma unroll
    for (int ii = 0; ii < 4; ii++) {
        m_i[ii] = -1e30f;
        l_i[ii] = 0.0f;
#pragma unroll
        for (int jj = 0; jj < 4; jj++) o[ii][jj] = 0.0f;
    }

    for (int kt0 = 0; kt0 < L_; kt0 += 64) {
        __syncthreads();
#pragma unroll
        for (int rep = 0; rep < 4; rep++) {
            int lin = tid + rep * 256;
            int d = lin >> 4, j4 = (lin & 15) * 4;
            *(float4*)&KP[d * 64 + j4] = *(const float4*)(Kg + (size_t)d * L_ + kt0 + j4);
        }
#pragma unroll
        for (int rep = 0; rep < 4; rep++) {
            int lin = tid + rep * 256;
            int j = lin >> 4, d4 = (lin & 15) * 4;
            *(float4*)&Vs[j * 64 + d4] = *(const float4*)(Vg + (size_t)(kt0 + j) * DH_ + d4);
        }
        __syncthreads();

        float s[4][4];
#pragma unroll
        for (int ii = 0; ii < 4; ii++)
#pragma unroll
            for (int jj = 0; jj < 4; jj++) s[ii][jj] = 0.0f;

#pragma unroll
        for (int d = 0; d < 64; d++) {
            float4 qv = *(float4*)&Qts[d * 64 + ty * 4];
            float4 kv = *(float4*)&KP[d * 64 + tx * 4];
            s[0][0] += qv.x * kv.x; s[0][1] += qv.x * kv.y; s[0][2] += qv.x * kv.z; s[0][3] += qv.x * kv.w;
            s[1][0] += qv.y * kv.x; s[1][1] += qv.y * kv.y; s[1][2] += qv.y * kv.z; s[1][3] += qv.y * kv.w;
            s[2][0] += qv.z * kv.x; s[2][1] += qv.z * kv.y; s[2][2] += qv.z * kv.z; s[2][3] += qv.z * kv.w;
            s[3][0] += qv.w * kv.x; s[3][1] += qv.w * kv.y; s[3][2] += qv.w * kv.z; s[3][3] += qv.w * kv.w;
        }

        float mb[4];
#pragma unroll
        for (int jj = 0; jj < 4; jj++)
            mb[jj] = mk[kt0 + tx * 4 + jj] ? -1e30f : 0.0f;
#pragma unroll
        for (int ii = 0; ii < 4; ii++)
#pragma unroll
            for (int jj = 0; jj < 4; jj++)
                s[ii][jj] = s[ii][jj] * SCALE_ + mb[jj];

        float p[4][4];
#pragma unroll
        for (int ii = 0; ii < 4; ii++) {
            float mx = fmaxf(fmaxf(s[ii][0], s[ii][1]), fmaxf(s[ii][2], s[ii][3]));
            mx = fmaxf(mx, __shfl_xor_sync(0xffffffffu, mx, 8));
            mx = fmaxf(mx, __shfl_xor_sync(0xffffffffu, mx, 4));
            mx = fmaxf(mx, __shfl_xor_sync(0xffffffffu, mx, 2));
            mx = fmaxf(mx, __shfl_xor_sync(0xffffffffu, mx, 1));
            float mnew = fmaxf(m_i[ii], mx);
            float alpha = __expf(m_i[ii] - mnew);
            m_i[ii] = mnew;
            float rs = 0.0f;
#pragma unroll
            for (int jj = 0; jj < 4; jj++) {
                p[ii][jj] = __expf(s[ii][jj] - mnew);
                rs += p[ii][jj];
            }
            rs += __shfl_xor_sync(0xffffffffu, rs, 8);
            rs += __shfl_xor_sync(0xffffffffu, rs, 4);
            rs += __shfl_xor_sync(0xffffffffu, rs, 2);
            rs += __shfl_xor_sync(0xffffffffu, rs, 1);
            l_i[ii] = l_i[ii] * alpha + rs;
#pragma unroll
            for (int jj = 0; jj < 4; jj++) o[ii][jj] *= alpha;
        }

        __syncthreads();
#pragma unroll
        for (int ii = 0; ii < 4; ii++)
#pragma unroll
            for (int jj = 0; jj < 4; jj++)
                KP[(ty * 4 + ii) * 64 + tx * 4 + jj] = p[ii][jj];
        __syncthreads();

#pragma unroll
        for (int j = 0; j < 64; j++) {
            float4 v = *(float4*)&Vs[j * 64 + tx * 4];
            float p0 = KP[(ty * 4 + 0) * 64 + j];
            float p1 = KP[(ty * 4 + 1) * 64 + j];
            float p2 = KP[(ty * 4 + 2) * 64 + j];
            float p3 = KP[(ty * 4 + 3) * 64 + j];
            o[0][0] += p0 * v.x; o[0][1] += p0 * v.y; o[0][2] += p0 * v.z; o[0][3] += p0 * v.w;
            o[1][0] += p1 * v.x; o[1][1] += p1 * v.y; o[1][2] += p1 * v.z; o[1][3] += p1 * v.w;
            o[2][0] += p2 * v.x; o[2][1] += p2 * v.y; o[2][2] += p2 * v.z; o[2][3] += p2 * v.w;
            o[3][0] += p3 * v.x; o[3][1] += p3 * v.y; o[3][2] += p3 * v.z; o[3][3] += p3 * v.w;
        }
    }

#pragma unroll
    for (int ii = 0; ii < 4; ii++) {
        float inv = 1.0f / l_i[ii];
        float4 r;
        r.x = o[ii][0] * inv; r.y = o[ii][1] * inv;
        r.z = o[ii][2] * inv; r.w = o[ii][3] * inv;
        size_t addr = ((size_t)(b * L_ + qt * 64 + ty * 4 + ii)) * D_ + h * DH_ + tx * 4;
        *(float4*)(g_O + addr) = r;
    }
}

// ---------------- launch ----------------
extern "C" void kernel_launch(void* const* d_in, const int* in_sizes, int n_in,
                              void* d_out, int out_size)
{
    const float* x     = (const float*)d_in[0];
    const float* w_qkv = (const float*)d_in[1];
    const float* b_qkv = (const float*)d_in[2];
    const float* w_out = (const float*)d_in[3];
    const float* b_out = (const float*)d_in[4];
    const void*  mask  = d_in[5];

    float* Optr = nullptr;
    cudaGetSymbolAddress((void**)&Optr, g_O);
    __nv_bfloat16 *Xh, *Xl, *Wqh, *Wql, *Woh, *Wol, *Oh, *Ol;
    cudaGetSymbolAddress((void**)&Xh,  g_Xh);
    cudaGetSymbolAddress((void**)&Xl,  g_Xl);
    cudaGetSymbolAddress((void**)&Wqh, g_Wqh);
    cudaGetSymbolAddress((void**)&Wql, g_Wql);
    cudaGetSymbolAddress((void**)&Woh, g_Woh);
    cudaGetSymbolAddress((void**)&Wol, g_Wol);
    cudaGetSymbolAddress((void**)&Oh,  g_Oh);
    cudaGetSymbolAddress((void**)&Ol,  g_Ol);

    cudaFuncSetAttribute(gemm_mma, cudaFuncAttributeMaxDynamicSharedMemorySize, GEMM_SMEM);

    k_reset<<<1, 32>>>();
    k_detect<<<4, 256>>>((const unsigned int*)mask, (B_ * L_) / 4);
    k_conv<<<(B_ * L_ + 255) / 256, 256>>>(mask, B_ * L_);

    // operand prep
    k_split<<<(M_ * K_ / 4 + 255) / 256, 256>>>(x, Xh, Xl, M_ * K_ / 4);
    k_splitT<<<dim3(3 * D_ / 32, K_ / 32), dim3(32, 8)>>>(w_qkv, Wqh, Wql, 3 * D_);
    k_splitT<<<dim3(D_ / 32, K_ / 32), dim3(32, 8)>>>(w_out, Woh, Wol, D_);

    // QKV projection (tensor cores via mma.sync) + scatter
    gemm_mma<<<dim3(3 * D_ / 128, M_ / 128), 256, GEMM_SMEM>>>(
        Xh, Xl, Wqh, Wql, b_qkv, nullptr, 3 * D_, 1);

    // attention (fp32)
    attn_kernel<<<dim3(L_ / 64, H_, B_), 256>>>();

    // output projection
    k_split<<<(M_ * D_ / 4 + 255) / 256, 256>>>(Optr, Oh, Ol, M_ * D_ / 4);
    gemm_mma<<<dim3(D_ / 128, M_ / 128), 256, GEMM_SMEM>>>(
        Oh, Ol, Woh, Wol, b_out, (float*)d_out, D_, 0);
}

// round 12
// speedup vs baseline: 2.7550x; 1.9144x over previous
#include <cuda_runtime.h>
#include <cuda_bf16.h>
#include <cstdint>

#define B_  2
#define L_  2048
#define D_  1024
#define H_  16
#define DH_ 64
#define M_  (B_ * L_)
#define K_  D_
#define SCALE_ 0.125f

// ---------------- scratch (no allocations allowed) ----------------
__device__ float g_mbias[B_ * L_];          // 0 or -1e30 per key
__device__ int   g_is_i32;

// bf16 split operands
__device__ __nv_bfloat16 g_Xh[M_ * K_],      g_Xl[M_ * K_];       // x [M,K]
__device__ __nv_bfloat16 g_Wqh[3 * D_ * K_], g_Wql[3 * D_ * K_];  // w_qkv^T [3072,K]
__device__ __nv_bfloat16 g_Woh[D_ * K_],     g_Wol[D_ * K_];      // w_out^T [1024,K]
__device__ __nv_bfloat16 g_Oh[M_ * D_],      g_Ol[M_ * D_];       // attn out [M,D]
// Q/K/V bf16 hi/lo, all [B,H,L,DH] (dh contiguous)
__device__ __nv_bfloat16 g_Qh[B_ * H_ * L_ * DH_], g_Ql[B_ * H_ * L_ * DH_];
__device__ __nv_bfloat16 g_Kh[B_ * H_ * L_ * DH_], g_Kl[B_ * H_ * L_ * DH_];
__device__ __nv_bfloat16 g_Vh[B_ * H_ * L_ * DH_], g_Vl[B_ * H_ * L_ * DH_];

// ---------------- mask dtype detect + convert ----------------
__global__ void k_reset() {
    if (threadIdx.x == 0 && blockIdx.x == 0) g_is_i32 = 1;
}
__global__ void k_detect(const unsigned int* __restrict__ p, int n4) {
    int i = blockIdx.x * blockDim.x + threadIdx.x;
    for (; i < n4; i += gridDim.x * blockDim.x) {
        if (p[i] > 1u) atomicExch(&g_is_i32, 0);
    }
}
__global__ void k_conv(const void* __restrict__ raw, int n) {
    int i = blockIdx.x * blockDim.x + threadIdx.x;
    if (i < n) {
        int v;
        if (g_is_i32) v = (((const int*)raw)[i] != 0) ? 1 : 0;
        else          v = (((const unsigned char*)raw)[i] != 0) ? 1 : 0;
        g_mbias[i] = v ? -1e30f : 0.0f;
    }
}

// ---------------- fp32 -> bf16 hi/lo split ----------------
__global__ void k_split(const float* __restrict__ in,
                        __nv_bfloat16* __restrict__ hi,
                        __nv_bfloat16* __restrict__ lo, int n4)
{
    int i = blockIdx.x * blockDim.x + threadIdx.x;
    if (i >= n4) return;
    float4 v = ((const float4*)in)[i];
    __nv_bfloat16 h0 = __float2bfloat16(v.x);
    __nv_bfloat16 h1 = __float2bfloat16(v.y);
    __nv_bfloat16 h2 = __float2bfloat16(v.z);
    __nv_bfloat16 h3 = __float2bfloat16(v.w);
    __nv_bfloat162* hp = (__nv_bfloat162*)hi;
    __nv_bfloat162* lp = (__nv_bfloat162*)lo;
    hp[2 * i + 0] = __nv_bfloat162(h0, h1);
    hp[2 * i + 1] = __nv_bfloat162(h2, h3);
    lp[2 * i + 0] = __nv_bfloat162(__float2bfloat16(v.x - __bfloat162float(h0)),
                                   __float2bfloat16(v.y - __bfloat162float(h1)));
    lp[2 * i + 1] = __nv_bfloat162(__float2bfloat16(v.z - __bfloat162float(h2)),
                                   __float2bfloat16(v.w - __bfloat162float(h3)));
}

// ---------------- fp32 [K,N] -> bf16 hi/lo [N,K] (split + transpose) --------
__global__ void k_splitT(const float* __restrict__ w,
                         __nv_bfloat16* __restrict__ hi,
                         __nv_bfloat16* __restrict__ lo, int N)
{
    __shared__ float t[32][33];
    int n0 = blockIdx.x * 32, k0 = blockIdx.y * 32;
    int tx = threadIdx.x, ty = threadIdx.y;   // 32 x 8
#pragma unroll
    for (int i = 0; i < 32; i += 8)
        t[ty + i][tx] = w[(size_t)(k0 + ty + i) * N + n0 + tx];
    __syncthreads();
#pragma unroll
    for (int i = 0; i < 32; i += 8) {
        float v = t[tx][ty + i];
        size_t o = (size_t)(n0 + ty + i) * K_ + k0 + tx;
        __nv_bfloat16 h = __float2bfloat16(v);
        hi[o] = h;
        lo[o] = __float2bfloat16(v - __bfloat162float(h));
    }
}

// ---------------- warp-mma helpers ----------------
__device__ __forceinline__ uint32_t smem_u32(const void* p) {
    uint32_t a;
    asm("{ .reg .u64 t; cvta.to.shared.u64 t, %1; cvt.u32.u64 %0, t; }"
        : "=r"(a) : "l"(p));
    return a;
}
__device__ __forceinline__ uint32_t swz(uint32_t off) { return off ^ ((off >> 3) & 0x70); }
__device__ __forceinline__ void ldm_x4(uint32_t* r, uint32_t addr) {
    asm volatile("ldmatrix.sync.aligned.m8n8.x4.shared.b16 {%0,%1,%2,%3}, [%4];"
                 : "=r"(r[0]), "=r"(r[1]), "=r"(r[2]), "=r"(r[3]) : "r"(addr));
}
__device__ __forceinline__ void ldm_x4t(uint32_t* r, uint32_t addr) {
    asm volatile("ldmatrix.sync.aligned.m8n8.x4.trans.shared.b16 {%0,%1,%2,%3}, [%4];"
                 : "=r"(r[0]), "=r"(r[1]), "=r"(r[2]), "=r"(r[3]) : "r"(addr));
}
__device__ __forceinline__ void mma_bf16(float* d, const uint32_t* a, const uint32_t* b) {
    asm volatile(
        "mma.sync.aligned.m16n8k16.row.col.f32.bf16.bf16.f32 "
        "{%0,%1,%2,%3}, {%4,%5,%6,%7}, {%8,%9}, {%0,%1,%2,%3};"
        : "+f"(d[0]), "+f"(d[1]), "+f"(d[2]), "+f"(d[3])
        : "r"(a[0]), "r"(a[1]), "r"(a[2]), "r"(a[3]), "r"(b[0]), "r"(b[1]));
}
__device__ __forceinline__ void cpasync16(uint32_t saddr, const void* g) {
    asm volatile("cp.async.cg.shared.global [%0], [%1], 16;" :: "r"(saddr), "l"(g));
}
__device__ __forceinline__ void cp_commit() {
    asm volatile("cp.async.commit_group;" ::: "memory");
}
__device__ __forceinline__ void pack_split(float f0, float f1, uint32_t& ph, uint32_t& pl) {
    __nv_bfloat162 h = __floats2bfloat162_rn(f0, f1);
    ph = *reinterpret_cast<uint32_t*>(&h);
    __nv_bfloat162 l = __floats2bfloat162_rn(f0 - __bfloat162float(h.x),
                                             f1 - __bfloat162float(h.y));
    pl = *reinterpret_cast<uint32_t*>(&l);
}

// ---------------- bf16-split GEMM via mma.sync: C = A * B^T + bias ----------
#define TILE_B   16384
#define BUF_B    (4 * TILE_B)
#define GEMM_SMEM (2 * BUF_B)

__global__ void __launch_bounds__(256, 1) gemm_mma(
    const __nv_bfloat16* __restrict__ Ah, const __nv_bfloat16* __restrict__ Al,
    const __nv_bfloat16* __restrict__ Bh, const __nv_bfloat16* __restrict__ Bl,
    const float* __restrict__ bias, float* __restrict__ C, int N, int mode)
{
    extern __shared__ __align__(1024) char smem[];
    const uint32_t sb = smem_u32(smem);
    const int tid = threadIdx.x, wid = tid >> 5, lid = tid & 31;
    const int warp_m = wid & 3, warp_n = wid >> 2;
    const int bm = blockIdx.y * 128, bn = blockIdx.x * 128;

    const __nv_bfloat16* srcs[4] = { Ah, Al, Bh, Bl };
    const int rbs[4] = { bm, bm, bn, bn };

    int lrow[4], lu[4]; uint32_t lso[4];
#pragma unroll
    for (int i = 0; i < 4; i++) {
        int un = tid + i * 256;
        lrow[i] = un >> 3; lu[i] = un & 7;
        lso[i] = swz(lrow[i] * 128 + lu[i] * 16);
    }

    auto load_chunk = [&](int c) {
        const int kt = c * 64;
        const uint32_t bo = sb + (c & 1) * BUF_B;
#pragma unroll
        for (int s = 0; s < 4; s++) {
            const __nv_bfloat16* src = srcs[s];
            const int rb = rbs[s];
#pragma unroll
            for (int i = 0; i < 4; i++)
                cpasync16(bo + s * TILE_B + lso[i],
                          src + (size_t)(rb + lrow[i]) * K_ + kt + lu[i] * 8);
        }
        cp_commit();
    };

    float acc[2][8][4];
#pragma unroll
    for (int i = 0; i < 2; i++)
#pragma unroll
        for (int j = 0; j < 8; j++)
#pragma unroll
            for (int e = 0; e < 4; e++) acc[i][j][e] = 0.0f;

    const int q4 = lid >> 3, rsub = lid & 7;
    const int a_r = (q4 & 1) * 8, a_k = (q4 >> 1) * 16;
    const int b_r = (q4 >> 1) * 8, b_k = (q4 & 1) * 16;

    load_chunk(0);

    for (int c = 0; c < 16; c++) {
        asm volatile("cp.async.wait_group 0;" ::: "memory");
        __syncthreads();
        if (c + 1 < 16) load_chunk(c + 1);

        const uint32_t bo = sb + (c & 1) * BUF_B;
        const uint32_t sAh = bo, sAl = bo + TILE_B;
        const uint32_t sBh = bo + 2 * TILE_B, sBl = bo + 3 * TILE_B;

#pragma unroll
        for (int ks = 0; ks < 4; ks++) {
            uint32_t ah[2][4], al[2][4];
#pragma unroll
            for (int i = 0; i < 2; i++) {
                uint32_t off = swz((uint32_t)(warp_m * 32 + i * 16 + a_r + rsub) * 128
                                   + ks * 32 + a_k);
                ldm_x4(ah[i], sAh + off);
                ldm_x4(al[i], sAl + off);
            }
#pragma unroll
            for (int nb = 0; nb < 4; nb++) {
                uint32_t bh[4], bl[4];
                uint32_t off = swz((uint32_t)(warp_n * 64 + nb * 16 + b_r + rsub) * 128
                                   + ks * 32 + b_k);
                ldm_x4(bh, sBh + off);
                ldm_x4(bl, sBl + off);
#pragma unroll
                for (int i = 0; i < 2; i++)
#pragma unroll
                    for (int t = 0; t < 2; t++) {
                        float* d = acc[i][nb * 2 + t];
                        mma_bf16(d, ah[i], bh + t * 2);
                        mma_bf16(d, ah[i], bl + t * 2);
                        mma_bf16(d, al[i], bh + t * 2);
                    }
            }
        }
        __syncthreads();
    }

    const int g = lid >> 2, t2 = (lid & 3) * 2;
#pragma unroll
    for (int i = 0; i < 2; i++) {
        const int r0 = bm + warp_m * 32 + i * 16 + g;
#pragma unroll
        for (int j = 0; j < 8; j++) {
            const int cn = bn + warp_n * 64 + j * 8 + t2;
            float v0 = acc[i][j][0] + bias[cn];
            float v1 = acc[i][j][1] + bias[cn + 1];
            float v2 = acc[i][j][2] + bias[cn];
            float v3 = acc[i][j][3] + bias[cn + 1];
            if (mode == 0) {
                C[(size_t)r0 * N + cn]           = v0;
                C[(size_t)r0 * N + cn + 1]       = v1;
                C[(size_t)(r0 + 8) * N + cn]     = v2;
                C[(size_t)(r0 + 8) * N + cn + 1] = v3;
            } else {
                const int which = cn >> 10, dd = cn & 1023;
                const int hh = dd >> 6, dh = dd & 63;
                __nv_bfloat16 *dsth, *dstl;
                if (which == 0)      { dsth = g_Qh; dstl = g_Ql; }
                else if (which == 1) { dsth = g_Kh; dstl = g_Kl; }
                else                 { dsth = g_Vh; dstl = g_Vl; }
#pragma unroll
                for (int rr = 0; rr < 2; rr++) {
                    const int r = r0 + rr * 8;
                    const int bb = r >> 11, ll = r & 2047;
                    const size_t idx = (((size_t)(bb * H_ + hh)) * L_ + ll) * DH_ + dh;
                    uint32_t ph, pl;
                    pack_split(rr ? v2 : v0, rr ? v3 : v1, ph, pl);
                    *reinterpret_cast<uint32_t*>(&dsth[idx]) = ph;
                    *reinterpret_cast<uint32_t*>(&dstl[idx]) = pl;
                }
            }
        }
    }
}

// ---------------- flash attention via mma.sync (bf16 hi/lo split) -----------
// CTA: 128 q rows x one (b,h). 8 warps x 16 rows. Key chunks of 64.
// smem: Qh|Ql 16KB each + 2 buffers x (Kh|Kl|Vh|Vl 8KB each) = 96KB.
#define AT_SMEM (32768 + 2 * 32768)

__global__ void __launch_bounds__(256, 2) attn_mma()
{
    extern __shared__ __align__(1024) char smem[];
    const uint32_t sb = smem_u32(smem);
    const int tid = threadIdx.x, wid = tid >> 5, lid = tid & 31;
    const int qt = blockIdx.x, h = blockIdx.y, b = blockIdx.z;

    const size_t head = ((size_t)(b * H_ + h)) * L_;
    const __nv_bfloat16* Qh = g_Qh + (head + qt * 128) * DH_;
    const __nv_bfloat16* Ql = g_Ql + (head + qt * 128) * DH_;
    const __nv_bfloat16* Kh = g_Kh + head * DH_;
    const __nv_bfloat16* Kl = g_Kl + head * DH_;
    const __nv_bfloat16* Vh = g_Vh + head * DH_;
    const __nv_bfloat16* Vl = g_Vl + head * DH_;
    const float* mb = g_mbias + b * L_;

    const uint32_t sQH = sb, sQL = sb + 16384;

    auto load_kv = [&](int c) {
        const uint32_t bo = sb + 32768 + (c & 1) * 32768;
        const int kt = c * 64;
#pragma unroll
        for (int i = 0; i < 2; i++) {
            int un = tid + i * 256;
            int row = un >> 3, u = un & 7;
            uint32_t o = swz(row * 128 + u * 16);
            const size_t gg = (size_t)(kt + row) * DH_ + u * 8;
            cpasync16(bo + o,         Kh + gg);
            cpasync16(bo + 8192 + o,  Kl + gg);
            cpasync16(bo + 16384 + o, Vh + gg);
            cpasync16(bo + 24576 + o, Vl + gg);
        }
    };

    // prologue: Q + chunk 0 (group 0), chunk 1 (group 1)
#pragma unroll
    for (int i = 0; i < 4; i++) {
        int un = tid + i * 256;
        int row = un >> 3, u = un & 7;
        uint32_t o = swz(row * 128 + u * 16);
        cpasync16(sQH + o, Qh + (size_t)row * DH_ + u * 8);
        cpasync16(sQL + o, Ql + (size_t)row * DH_ + u * 8);
    }
    load_kv(0);
    cp_commit();
    load_kv(1);
    cp_commit();

    float oacc[8][4];
#pragma unroll
    for (int nb = 0; nb < 8; nb++)
#pragma unroll
        for (int e = 0; e < 4; e++) oacc[nb][e] = 0.0f;
    float m0 = -1e30f, m1 = -1e30f, l0 = 0.0f, l1 = 0.0f;

    const int q4 = lid >> 3, rsub = lid & 7;
    const int a_r = (q4 & 1) * 8, a_k = (q4 >> 1) * 16;  // A / trans-B components
    const int b_r = (q4 >> 1) * 8, b_k = (q4 & 1) * 16;  // non-trans B components
    const int g = lid >> 2, t2 = (lid & 3) * 2;

    asm volatile("cp.async.wait_group 1;" ::: "memory");
    __syncthreads();

    for (int c = 0; c < 32; c++) {
        const uint32_t bo = sb + 32768 + (c & 1) * 32768;
        const int kt0 = c * 64;

        // ---- S = Q K^T (3-way split) ----
        float sacc[8][4];
#pragma unroll
        for (int nb = 0; nb < 8; nb++)
#pragma unroll
            for (int e = 0; e < 4; e++) sacc[nb][e] = 0.0f;

#pragma unroll
        for (int ks = 0; ks < 4; ks++) {
            uint32_t qh[4], ql[4];
            uint32_t qo = swz((uint32_t)(wid * 16 + a_r + rsub) * 128 + ks * 32 + a_k);
            ldm_x4(qh, sQH + qo);
            ldm_x4(ql, sQL + qo);
#pragma unroll
            for (int nb2 = 0; nb2 < 4; nb2++) {
                uint32_t kh[4], kl[4];
                uint32_t ko = swz((uint32_t)(nb2 * 16 + b_r + rsub) * 128 + ks * 32 + b_k);
                ldm_x4(kh, bo + ko);
                ldm_x4(kl, bo + 8192 + ko);
#pragma unroll
                for (int t = 0; t < 2; t++) {
                    float* d = sacc[nb2 * 2 + t];
                    mma_bf16(d, qh, kh + 2 * t);
                    mma_bf16(d, qh, kl + 2 * t);
                    mma_bf16(d, ql, kh + 2 * t);
                }
            }
        }

        // ---- scale + key-padding mask ----
#pragma unroll
        for (int nb = 0; nb < 8; nb++) {
            float mb0 = mb[kt0 + nb * 8 + t2];
            float mb1 = mb[kt0 + nb * 8 + t2 + 1];
            sacc[nb][0] = sacc[nb][0] * SCALE_ + mb0;
            sacc[nb][1] = sacc[nb][1] * SCALE_ + mb1;
            sacc[nb][2] = sacc[nb][2] * SCALE_ + mb0;
            sacc[nb][3] = sacc[nb][3] * SCALE_ + mb1;
        }

        // ---- online softmax (rows g and g+8; quad-reduce over 4 lanes) ----
        float mx0 = -1e30f, mx1 = -1e30f;
#pragma unroll
        for (int nb = 0; nb < 8; nb++) {
            mx0 = fmaxf(mx0, fmaxf(sacc[nb][0], sacc[nb][1]));
            mx1 = fmaxf(mx1, fmaxf(sacc[nb][2], sacc[nb][3]));
        }
        mx0 = fmaxf(mx0, __shfl_xor_sync(0xffffffffu, mx0, 1));
        mx0 = fmaxf(mx0, __shfl_xor_sync(0xffffffffu, mx0, 2));
        mx1 = fmaxf(mx1, __shfl_xor_sync(0xffffffffu, mx1, 1));
        mx1 = fmaxf(mx1, __shfl_xor_sync(0xffffffffu, mx1, 2));
        float mn0 = fmaxf(m0, mx0), mn1 = fmaxf(m1, mx1);
        float al0 = __expf(m0 - mn0), al1 = __expf(m1 - mn1);
        m0 = mn0; m1 = mn1;

        float rs0 = 0.0f, rs1 = 0.0f;
#pragma unroll
        for (int nb = 0; nb < 8; nb++) {
            sacc[nb][0] = __expf(sacc[nb][0] - m0); rs0 += sacc[nb][0];
            sacc[nb][1] = __expf(sacc[nb][1] - m0); rs0 += sacc[nb][1];
            sacc[nb][2] = __expf(sacc[nb][2] - m1); rs1 += sacc[nb][2];
            sacc[nb][3] = __expf(sacc[nb][3] - m1); rs1 += sacc[nb][3];
        }
        rs0 += __shfl_xor_sync(0xffffffffu, rs0, 1);
        rs0 += __shfl_xor_sync(0xffffffffu, rs0, 2);
        rs1 += __shfl_xor_sync(0xffffffffu, rs1, 1);
        rs1 += __shfl_xor_sync(0xffffffffu, rs1, 2);
        l0 = l0 * al0 + rs0;
        l1 = l1 * al1 + rs1;
#pragma unroll
        for (int nb = 0; nb < 8; nb++) {
            oacc[nb][0] *= al0; oacc[nb][1] *= al0;
            oacc[nb][2] *= al1; oacc[nb][3] *= al1;
        }

        // ---- O += P V (P from registers; V via ldmatrix.trans; 3-way split) --
#pragma unroll
        for (int ks = 0; ks < 4; ks++) {
            uint32_t pah[4], pal[4];
            pack_split(sacc[2 * ks][0],     sacc[2 * ks][1],     pah[0], pal[0]);
            pack_split(sacc[2 * ks][2],     sacc[2 * ks][3],     pah[1], pal[1]);
            pack_split(sacc[2 * ks + 1][0], sacc[2 * ks + 1][1], pah[2], pal[2]);
            pack_split(sacc[2 * ks + 1][2], sacc[2 * ks + 1][3], pah[3], pal[3]);
#pragma unroll
            for (int nb2 = 0; nb2 < 4; nb2++) {
                uint32_t vh[4], vl[4];
                uint32_t vo = swz((uint32_t)(ks * 16 + a_r + rsub) * 128
                                  + nb2 * 32 + a_k);
                ldm_x4t(vh, bo + 16384 + vo);
                ldm_x4t(vl, bo + 24576 + vo);
#pragma unroll
                for (int t = 0; t < 2; t++) {
                    float* d = oacc[nb2 * 2 + t];
                    mma_bf16(d, pah, vh + 2 * t);
                    mma_bf16(d, pah, vl + 2 * t);
                    mma_bf16(d, pal, vh + 2 * t);
                }
            }
        }

        __syncthreads();
        if (c + 2 < 32) load_kv(c + 2);
        cp_commit();
        if (c + 1 < 32) {
            asm volatile("cp.async.wait_group 1;" ::: "memory");
            __syncthreads();
        }
    }

    // ---- epilogue: normalize, bf16 hi/lo split, write Oh/Ol [M,D] ----
    const float inv0 = 1.0f / l0, inv1 = 1.0f / l1;
    const int qrow = qt * 128 + wid * 16 + g;
    const size_t row0 = (size_t)(b * L_ + qrow) * D_;
    const size_t row1 = row0 + (size_t)8 * D_;
#pragma unroll
    for (int nb = 0; nb < 8; nb++) {
        const int col = h * 64 + nb * 8 + t2;
        uint32_t ph, pl;
        pack_split(oacc[nb][0] * inv0, oacc[nb][1] * inv0, ph, pl);
        *reinterpret_cast<uint32_t*>(&g_Oh[row0 + col]) = ph;
        *reinterpret_cast<uint32_t*>(&g_Ol[row0 + col]) = pl;
        pack_split(oacc[nb][2] * inv1, oacc[nb][3] * inv1, ph, pl);
        *reinterpret_cast<uint32_t*>(&g_Oh[row1 + col]) = ph;
        *reinterpret_cast<uint32_t*>(&g_Ol[row1 + col]) = pl;
    }
}

// ---------------- launch ----------------
extern "C" void kernel_launch(void* const* d_in, const int* in_sizes, int n_in,
                              void* d_out, int out_size)
{
    const float* x     = (const float*)d_in[0];
    const float* w_qkv = (const float*)d_in[1];
    const float* b_qkv = (const float*)d_in[2];
    const float* w_out = (const float*)d_in[3];
    const float* b_out = (const float*)d_in[4];
    const void*  mask  = d_in[5];

    __nv_bfloat16 *Xh, *Xl, *Wqh, *Wql, *Woh, *Wol, *Oh, *Ol;
    cudaGetSymbolAddress((void**)&Xh,  g_Xh);
    cudaGetSymbolAddress((void**)&Xl,  g_Xl);
    cudaGetSymbolAddress((void**)&Wqh, g_Wqh);
    cudaGetSymbolAddress((void**)&Wql, g_Wql);
    cudaGetSymbolAddress((void**)&Woh, g_Woh);
    cudaGetSymbolAddress((void**)&Wol, g_Wol);
    cudaGetSymbolAddress((void**)&Oh,  g_Oh);
    cudaGetSymbolAddress((void**)&Ol,  g_Ol);

    cudaFuncSetAttribute(gemm_mma, cudaFuncAttributeMaxDynamicSharedMemorySize, GEMM_SMEM);
    cudaFuncSetAttribute(attn_mma, cudaFuncAttributeMaxDynamicSharedMemorySize, AT_SMEM);

    k_reset<<<1, 32>>>();
    k_detect<<<4, 256>>>((const unsigned int*)mask, (B_ * L_) / 4);
    k_conv<<<(B_ * L_ + 255) / 256, 256>>>(mask, B_ * L_);

    // operand prep
    k_split<<<(M_ * K_ / 4 + 255) / 256, 256>>>(x, Xh, Xl, M_ * K_ / 4);
    k_splitT<<<dim3(3 * D_ / 32, K_ / 32), dim3(32, 8)>>>(w_qkv, Wqh, Wql, 3 * D_);
    k_splitT<<<dim3(D_ / 32, K_ / 32), dim3(32, 8)>>>(w_out, Woh, Wol, D_);

    // QKV projection -> bf16 hi/lo Q/K/V [B,H,L,DH]
    gemm_mma<<<dim3(3 * D_ / 128, M_ / 128), 256, GEMM_SMEM>>>(
        Xh, Xl, Wqh, Wql, b_qkv, nullptr, 3 * D_, 1);

    // flash attention (tensor cores) -> writes g_Oh/g_Ol directly
    attn_mma<<<dim3(L_ / 128, H_, B_), 256, AT_SMEM>>>();

    // output projection
    gemm_mma<<<dim3(D_ / 128, M_ / 128), 256, GEMM_SMEM>>>(
        Oh, Ol, Woh, Wol, b_out, (float*)d_out, D_, 0);
}

// round 14
// speedup vs baseline: 3.3432x; 1.2135x over previous
#include <cuda_runtime.h>
#include <cuda_bf16.h>
#include <cuda_fp16.h>
#include <cstdint>

#define B_  2
#define L_  2048
#define D_  1024
#define H_  16
#define DH_ 64
#define M_  (B_ * L_)
#define K_  D_
#define SCALE_ 0.125f

// ---------------- scratch (no allocations allowed) ----------------
__device__ float g_mbias[B_ * L_];          // 0 or -1e30 per key
__device__ int   g_is_i32;
__device__ int   g_kvlen[B_];               // 1 + last unmasked key index

// bf16 split operands for the two projections
__device__ __nv_bfloat16 g_Xh[M_ * K_],      g_Xl[M_ * K_];       // x [M,K]
__device__ __nv_bfloat16 g_Wqh[3 * D_ * K_], g_Wql[3 * D_ * K_];  // w_qkv^T [3072,K]
__device__ __nv_bfloat16 g_Woh[D_ * K_],     g_Wol[D_ * K_];      // w_out^T [1024,K]
__device__ __nv_bfloat16 g_Oh[M_ * D_],      g_Ol[M_ * D_];       // attn out [M,D]
// attention operands, fp16, [B,H,L,DH] (dh contiguous)
__device__ __half g_Qf[B_ * H_ * L_ * DH_];                        // Q single fp16
__device__ __half g_Khh[B_ * H_ * L_ * DH_], g_Khl[B_ * H_ * L_ * DH_];
__device__ __half g_Vhh[B_ * H_ * L_ * DH_], g_Vhl[B_ * H_ * L_ * DH_];

// ---------------- mask dtype detect + convert ----------------
__global__ void k_reset() {
    if (threadIdx.x == 0 && blockIdx.x == 0) {
        g_is_i32 = 1;
        for (int i = 0; i < B_; i++) g_kvlen[i] = 0;
    }
}
__global__ void k_detect(const unsigned int* __restrict__ p, int n4) {
    int i = blockIdx.x * blockDim.x + threadIdx.x;
    for (; i < n4; i += gridDim.x * blockDim.x) {
        if (p[i] > 1u) atomicExch(&g_is_i32, 0);
    }
}
__global__ void k_conv(const void* __restrict__ raw, int n) {
    int i = blockIdx.x * blockDim.x + threadIdx.x;
    if (i < n) {
        int v;
        if (g_is_i32) v = (((const int*)raw)[i] != 0) ? 1 : 0;
        else          v = (((const unsigned char*)raw)[i] != 0) ? 1 : 0;
        g_mbias[i] = v ? -1e30f : 0.0f;
        if (!v) atomicMax(&g_kvlen[i >> 11], (i & (L_ - 1)) + 1);
    }
}

// ---------------- fp32 -> bf16 hi/lo split ----------------
__global__ void k_split(const float* __restrict__ in,
                        __nv_bfloat16* __restrict__ hi,
                        __nv_bfloat16* __restrict__ lo, int n4)
{
    int i = blockIdx.x * blockDim.x + threadIdx.x;
    if (i >= n4) return;
    float4 v = ((const float4*)in)[i];
    __nv_bfloat16 h0 = __float2bfloat16(v.x);
    __nv_bfloat16 h1 = __float2bfloat16(v.y);
    __nv_bfloat16 h2 = __float2bfloat16(v.z);
    __nv_bfloat16 h3 = __float2bfloat16(v.w);
    __nv_bfloat162* hp = (__nv_bfloat162*)hi;
    __nv_bfloat162* lp = (__nv_bfloat162*)lo;
    hp[2 * i + 0] = __nv_bfloat162(h0, h1);
    hp[2 * i + 1] = __nv_bfloat162(h2, h3);
    lp[2 * i + 0] = __nv_bfloat162(__float2bfloat16(v.x - __bfloat162float(h0)),
                                   __float2bfloat16(v.y - __bfloat162float(h1)));
    lp[2 * i + 1] = __nv_bfloat162(__float2bfloat16(v.z - __bfloat162float(h2)),
                                   __float2bfloat16(v.w - __bfloat162float(h3)));
}

// ---------------- fp32 [K,N] -> bf16 hi/lo [N,K] (split + transpose) --------
__global__ void k_splitT(const float* __restrict__ w,
                         __nv_bfloat16* __restrict__ hi,
                         __nv_bfloat16* __restrict__ lo, int N)
{
    __shared__ float t[32][33];
    int n0 = blockIdx.x * 32, k0 = blockIdx.y * 32;
    int tx = threadIdx.x, ty = threadIdx.y;   // 32 x 8
#pragma unroll
    for (int i = 0; i < 32; i += 8)
        t[ty + i][tx] = w[(size_t)(k0 + ty + i) * N + n0 + tx];
    __syncthreads();
#pragma unroll
    for (int i = 0; i < 32; i += 8) {
        float v = t[tx][ty + i];
        size_t o = (size_t)(n0 + ty + i) * K_ + k0 + tx;
        __nv_bfloat16 h = __float2bfloat16(v);
        hi[o] = h;
        lo[o] = __float2bfloat16(v - __bfloat162float(h));
    }
}

// ---------------- warp-mma helpers ----------------
__device__ __forceinline__ uint32_t smem_u32(const void* p) {
    uint32_t a;
    asm("{ .reg .u64 t; cvta.to.shared.u64 t, %1; cvt.u32.u64 %0, t; }"
        : "=r"(a) : "l"(p));
    return a;
}
__device__ __forceinline__ uint32_t swz(uint32_t off) { return off ^ ((off >> 3) & 0x70); }
__device__ __forceinline__ void ldm_x4(uint32_t* r, uint32_t addr) {
    asm volatile("ldmatrix.sync.aligned.m8n8.x4.shared.b16 {%0,%1,%2,%3}, [%4];"
                 : "=r"(r[0]), "=r"(r[1]), "=r"(r[2]), "=r"(r[3]) : "r"(addr));
}
__device__ __forceinline__ void ldm_x4t(uint32_t* r, uint32_t addr) {
    asm volatile("ldmatrix.sync.aligned.m8n8.x4.trans.shared.b16 {%0,%1,%2,%3}, [%4];"
                 : "=r"(r[0]), "=r"(r[1]), "=r"(r[2]), "=r"(r[3]) : "r"(addr));
}
__device__ __forceinline__ void mma_bf16(float* d, const uint32_t* a, const uint32_t* b) {
    asm volatile(
        "mma.sync.aligned.m16n8k16.row.col.f32.bf16.bf16.f32 "
        "{%0,%1,%2,%3}, {%4,%5,%6,%7}, {%8,%9}, {%0,%1,%2,%3};"
        : "+f"(d[0]), "+f"(d[1]), "+f"(d[2]), "+f"(d[3])
        : "r"(a[0]), "r"(a[1]), "r"(a[2]), "r"(a[3]), "r"(b[0]), "r"(b[1]));
}
__device__ __forceinline__ void mma_f16(float* d, const uint32_t* a, const uint32_t* b) {
    asm volatile(
        "mma.sync.aligned.m16n8k16.row.col.f32.f16.f16.f32 "
        "{%0,%1,%2,%3}, {%4,%5,%6,%7}, {%8,%9}, {%0,%1,%2,%3};"
        : "+f"(d[0]), "+f"(d[1]), "+f"(d[2]), "+f"(d[3])
        : "r"(a[0]), "r"(a[1]), "r"(a[2]), "r"(a[3]), "r"(b[0]), "r"(b[1]));
}
__device__ __forceinline__ void cpasync16(uint32_t saddr, const void* g) {
    asm volatile("cp.async.cg.shared.global [%0], [%1], 16;" :: "r"(saddr), "l"(g));
}
__device__ __forceinline__ void cp_commit() {
    asm volatile("cp.async.commit_group;" ::: "memory");
}
__device__ __forceinline__ void pack_split(float f0, float f1, uint32_t& ph, uint32_t& pl) {
    __nv_bfloat162 h = __floats2bfloat162_rn(f0, f1);
    ph = *reinterpret_cast<uint32_t*>(&h);
    __nv_bfloat162 l = __floats2bfloat162_rn(f0 - __bfloat162float(h.x),
                                             f1 - __bfloat162float(h.y));
    pl = *reinterpret_cast<uint32_t*>(&l);
}
__device__ __forceinline__ void pack_split_f16(float f0, float f1, uint32_t& ph, uint32_t& pl) {
    __half2 h = __floats2half2_rn(f0, f1);
    ph = *reinterpret_cast<uint32_t*>(&h);
    __half2 l = __floats2half2_rn(f0 - __half2float(__low2half(h)),
                                  f1 - __half2float(__high2half(h)));
    pl = *reinterpret_cast<uint32_t*>(&l);
}
__device__ __forceinline__ uint32_t pack_f16(float f0, float f1) {
    __half2 h = __floats2half2_rn(f0, f1);
    return *reinterpret_cast<uint32_t*>(&h);
}

// ---------------- bf16-split GEMM via mma.sync: C = A * B^T + bias ----------
#define TILE_B   16384
#define BUF_B    (4 * TILE_B)
#define GEMM_SMEM (2 * BUF_B)

__global__ void __launch_bounds__(256, 1) gemm_mma(
    const __nv_bfloat16* __restrict__ Ah, const __nv_bfloat16* __restrict__ Al,
    const __nv_bfloat16* __restrict__ Bh, const __nv_bfloat16* __restrict__ Bl,
    const float* __restrict__ bias, float* __restrict__ C, int N, int mode)
{
    extern __shared__ __align__(1024) char smem[];
    const uint32_t sb = smem_u32(smem);
    const int tid = threadIdx.x, wid = tid >> 5, lid = tid & 31;
    const int warp_m = wid & 3, warp_n = wid >> 2;
    const int bm = blockIdx.y * 128, bn = blockIdx.x * 128;

    const __nv_bfloat16* srcs[4] = { Ah, Al, Bh, Bl };
    const int rbs[4] = { bm, bm, bn, bn };

    int lrow[4], lu[4]; uint32_t lso[4];
#pragma unroll
    for (int i = 0; i < 4; i++) {
        int un = tid + i * 256;
        lrow[i] = un >> 3; lu[i] = un & 7;
        lso[i] = swz(lrow[i] * 128 + lu[i] * 16);
    }

    auto load_chunk = [&](int c) {
        const int kt = c * 64;
        const uint32_t bo = sb + (c & 1) * BUF_B;
#pragma unroll
        for (int s = 0; s < 4; s++) {
            const __nv_bfloat16* src = srcs[s];
            const int rb = rbs[s];
#pragma unroll
            for (int i = 0; i < 4; i++)
                cpasync16(bo + s * TILE_B + lso[i],
                          src + (size_t)(rb + lrow[i]) * K_ + kt + lu[i] * 8);
        }
        cp_commit();
    };

    float acc[2][8][4];
#pragma unroll
    for (int i = 0; i < 2; i++)
#pragma unroll
        for (int j = 0; j < 8; j++)
#pragma unroll
            for (int e = 0; e < 4; e++) acc[i][j][e] = 0.0f;

    const int q4 = lid >> 3, rsub = lid & 7;
    const int a_r = (q4 & 1) * 8, a_k = (q4 >> 1) * 16;
    const int b_r = (q4 >> 1) * 8, b_k = (q4 & 1) * 16;

    load_chunk(0);

    for (int c = 0; c < 16; c++) {
        asm volatile("cp.async.wait_group 0;" ::: "memory");
        __syncthreads();
        if (c + 1 < 16) load_chunk(c + 1);

        const uint32_t bo = sb + (c & 1) * BUF_B;
        const uint32_t sAh = bo, sAl = bo + TILE_B;
        const uint32_t sBh = bo + 2 * TILE_B, sBl = bo + 3 * TILE_B;

#pragma unroll
        for (int ks = 0; ks < 4; ks++) {
            uint32_t ah[2][4], al[2][4];
#pragma unroll
            for (int i = 0; i < 2; i++) {
                uint32_t off = swz((uint32_t)(warp_m * 32 + i * 16 + a_r + rsub) * 128
                                   + ks * 32 + a_k);
                ldm_x4(ah[i], sAh + off);
                ldm_x4(al[i], sAl + off);
            }
#pragma unroll
            for (int nb = 0; nb < 4; nb++) {
                uint32_t bh[4], bl[4];
                uint32_t off = swz((uint32_t)(warp_n * 64 + nb * 16 + b_r + rsub) * 128
                                   + ks * 32 + b_k);
                ldm_x4(bh, sBh + off);
                ldm_x4(bl, sBl + off);
#pragma unroll
                for (int i = 0; i < 2; i++)
#pragma unroll
                    for (int t = 0; t < 2; t++) {
                        float* d = acc[i][nb * 2 + t];
                        mma_bf16(d, ah[i], bh + t * 2);
                        mma_bf16(d, ah[i], bl + t * 2);
                        mma_bf16(d, al[i], bh + t * 2);
                    }
            }
        }
        __syncthreads();
    }

    const int g = lid >> 2, t2 = (lid & 3) * 2;
#pragma unroll
    for (int i = 0; i < 2; i++) {
        const int r0 = bm + warp_m * 32 + i * 16 + g;
#pragma unroll
        for (int j = 0; j < 8; j++) {
            const int cn = bn + warp_n * 64 + j * 8 + t2;
            float v0 = acc[i][j][0] + bias[cn];
            float v1 = acc[i][j][1] + bias[cn + 1];
            float v2 = acc[i][j][2] + bias[cn];
            float v3 = acc[i][j][3] + bias[cn + 1];
            if (mode == 0) {
                C[(size_t)r0 * N + cn]           = v0;
                C[(size_t)r0 * N + cn + 1]       = v1;
                C[(size_t)(r0 + 8) * N + cn]     = v2;
                C[(size_t)(r0 + 8) * N + cn + 1] = v3;
            } else {
                const int which = cn >> 10, dd = cn & 1023;
                const int hh = dd >> 6, dh = dd & 63;
#pragma unroll
                for (int rr = 0; rr < 2; rr++) {
                    const int r = r0 + rr * 8;
                    const int bb = r >> 11, ll = r & 2047;
                    const size_t idx = (((size_t)(bb * H_ + hh)) * L_ + ll) * DH_ + dh;
                    const float f0 = rr ? v2 : v0, f1 = rr ? v3 : v1;
                    if (which == 0) {
                        *reinterpret_cast<uint32_t*>(&g_Qf[idx]) = pack_f16(f0, f1);
                    } else {
                        uint32_t ph, pl;
                        pack_split_f16(f0, f1, ph, pl);
                        __half* dsth = (which == 1) ? g_Khh : g_Vhh;
                        __half* dstl = (which == 1) ? g_Khl : g_Vhl;
                        *reinterpret_cast<uint32_t*>(&dsth[idx]) = ph;
                        *reinterpret_cast<uint32_t*>(&dstl[idx]) = pl;
                    }
                }
            }
        }
    }
}

// ---------------- flash attention via mma.sync (fp16; K/V hi/lo split) ------
// CTA: 128 q rows x one (b,h). 8 warps x 16 rows. Key chunks of 64.
// smem: Qf 16KB + 2 buffers x (Kh|Kl|Vh|Vl 8KB each) = 80KB.
#define AT_SMEM (16384 + 2 * 32768)

__global__ void __launch_bounds__(256, 2) attn_mma()
{
    extern __shared__ __align__(1024) char smem[];
    const uint32_t sb = smem_u32(smem);
    const int tid = threadIdx.x, wid = tid >> 5, lid = tid & 31;
    const int qt = blockIdx.x, h = blockIdx.y, b = blockIdx.z;

    const size_t head = ((size_t)(b * H_ + h)) * L_;
    const __half* Qf = g_Qf  + (head + qt * 128) * DH_;
    const __half* Kh = g_Khh + head * DH_;
    const __half* Kl = g_Khl + head * DH_;
    const __half* Vh = g_Vhh + head * DH_;
    const __half* Vl = g_Vhl + head * DH_;
    const float* mb = g_mbias + b * L_;
    const int nc = min(32, (g_kvlen[b] + 63) >> 6);   // chunks with any live key

    const uint32_t sQ = sb;

    auto load_kv = [&](int c) {
        const uint32_t bo = sb + 16384 + (c & 1) * 32768;
        const int kt = c * 64;
#pragma unroll
        for (int i = 0; i < 2; i++) {
            int un = tid + i * 256;
            int row = un >> 3, u = un & 7;
            uint32_t o = swz(row * 128 + u * 16);
            const size_t gg = (size_t)(kt + row) * DH_ + u * 8;
            cpasync16(bo + o,         Kh + gg);
            cpasync16(bo + 8192 + o,  Kl + gg);
            cpasync16(bo + 16384 + o, Vh + gg);
            cpasync16(bo + 24576 + o, Vl + gg);
        }
    };

    // prologue: Q + chunk 0 (group 0), chunk 1 (group 1, possibly empty)
#pragma unroll
    for (int i = 0; i < 4; i++) {
        int un = tid + i * 256;
        int row = un >> 3, u = un & 7;
        cpasync16(sQ + swz(row * 128 + u * 16), Qf + (size_t)row * DH_ + u * 8);
    }
    load_kv(0);
    cp_commit();
    if (nc > 1) load_kv(1);
    cp_commit();

    float oacc[8][4];
#pragma unroll
    for (int nb = 0; nb < 8; nb++)
#pragma unroll
        for (int e = 0; e < 4; e++) oacc[nb][e] = 0.0f;
    float m0 = -1e30f, m1 = -1e30f, l0 = 0.0f, l1 = 0.0f;

    const int q4 = lid >> 3, rsub = lid & 7;
    const int a_r = (q4 & 1) * 8, a_k = (q4 >> 1) * 16;  // A / trans-B components
    const int b_r = (q4 >> 1) * 8, b_k = (q4 & 1) * 16;  // non-trans B components
    const int g = lid >> 2, t2 = (lid & 3) * 2;

    asm volatile("cp.async.wait_group 1;" ::: "memory");
    __syncthreads();

    for (int c = 0; c < nc; c++) {
        const uint32_t bo = sb + 16384 + (c & 1) * 32768;
        const int kt0 = c * 64;

        // ---- S = Q K^T (Q single fp16, K hi/lo: 2 MMAs) ----
        float sacc[8][4];
#pragma unroll
        for (int nb = 0; nb < 8; nb++)
#pragma unroll
            for (int e = 0; e < 4; e++) sacc[nb][e] = 0.0f;

#pragma unroll
        for (int ks = 0; ks < 4; ks++) {
            uint32_t qf[4];
            ldm_x4(qf, sQ + swz((uint32_t)(wid * 16 + a_r + rsub) * 128 + ks * 32 + a_k));
#pragma unroll
            for (int nb2 = 0; nb2 < 4; nb2++) {
                uint32_t kh[4], kl[4];
                uint32_t ko = swz((uint32_t)(nb2 * 16 + b_r + rsub) * 128 + ks * 32 + b_k);
                ldm_x4(kh, bo + ko);
                ldm_x4(kl, bo + 8192 + ko);
#pragma unroll
                for (int t = 0; t < 2; t++) {
                    float* d = sacc[nb2 * 2 + t];
                    mma_f16(d, qf, kh + 2 * t);
                    mma_f16(d, qf, kl + 2 * t);
                }
            }
        }

        // ---- scale + key-padding mask ----
#pragma unroll
        for (int nb = 0; nb < 8; nb++) {
            float mb0 = mb[kt0 + nb * 8 + t2];
            float mb1 = mb[kt0 + nb * 8 + t2 + 1];
            sacc[nb][0] = sacc[nb][0] * SCALE_ + mb0;
            sacc[nb][1] = sacc[nb][1] * SCALE_ + mb1;
            sacc[nb][2] = sacc[nb][2] * SCALE_ + mb0;
            sacc[nb][3] = sacc[nb][3] * SCALE_ + mb1;
        }

        // ---- online softmax (rows g and g+8; quad-reduce over 4 lanes) ----
        float mx0 = -1e30f, mx1 = -1e30f;
#pragma unroll
        for (int nb = 0; nb < 8; nb++) {
            mx0 = fmaxf(mx0, fmaxf(sacc[nb][0], sacc[nb][1]));
            mx1 = fmaxf(mx1, fmaxf(sacc[nb][2], sacc[nb][3]));
        }
        mx0 = fmaxf(mx0, __shfl_xor_sync(0xffffffffu, mx0, 1));
        mx0 = fmaxf(mx0, __shfl_xor_sync(0xffffffffu, mx0, 2));
        mx1 = fmaxf(mx1, __shfl_xor_sync(0xffffffffu, mx1, 1));
        mx1 = fmaxf(mx1, __shfl_xor_sync(0xffffffffu, mx1, 2));
        float mn0 = fmaxf(m0, mx0), mn1 = fmaxf(m1, mx1);
        float al0 = __expf(m0 - mn0), al1 = __expf(m1 - mn1);
        m0 = mn0; m1 = mn1;

        float rs0 = 0.0f, rs1 = 0.0f;
#pragma unroll
        for (int nb = 0; nb < 8; nb++) {
            sacc[nb][0] = __expf(sacc[nb][0] - m0); rs0 += sacc[nb][0];
            sacc[nb][1] = __expf(sacc[nb][1] - m0); rs0 += sacc[nb][1];
            sacc[nb][2] = __expf(sacc[nb][2] - m1); rs1 += sacc[nb][2];
            sacc[nb][3] = __expf(sacc[nb][3] - m1); rs1 += sacc[nb][3];
        }
        rs0 += __shfl_xor_sync(0xffffffffu, rs0, 1);
        rs0 += __shfl_xor_sync(0xffffffffu, rs0, 2);
        rs1 += __shfl_xor_sync(0xffffffffu, rs1, 1);
        rs1 += __shfl_xor_sync(0xffffffffu, rs1, 2);
        l0 = l0 * al0 + rs0;
        l1 = l1 * al1 + rs1;
#pragma unroll
        for (int nb = 0; nb < 8; nb++) {
            oacc[nb][0] *= al0; oacc[nb][1] *= al0;
            oacc[nb][2] *= al1; oacc[nb][3] *= al1;
        }

        // ---- O += P V (P single fp16 from regs; V hi/lo via ldm.trans: 2 MMAs)
#pragma unroll
        for (int ks = 0; ks < 4; ks++) {
            uint32_t pa[4];
            pa[0] = pack_f16(sacc[2 * ks][0],     sacc[2 * ks][1]);
            pa[1] = pack_f16(sacc[2 * ks][2],     sacc[2 * ks][3]);
            pa[2] = pack_f16(sacc[2 * ks + 1][0], sacc[2 * ks + 1][1]);
            pa[3] = pack_f16(sacc[2 * ks + 1][2], sacc[2 * ks + 1][3]);
#pragma unroll
            for (int nb2 = 0; nb2 < 4; nb2++) {
                uint32_t vh[4], vl[4];
                uint32_t vo = swz((uint32_t)(ks * 16 + a_r + rsub) * 128
                                  + nb2 * 32 + a_k);
                ldm_x4t(vh, bo + 16384 + vo);
                ldm_x4t(vl, bo + 24576 + vo);
#pragma unroll
                for (int t = 0; t < 2; t++) {
                    float* d = oacc[nb2 * 2 + t];
                    mma_f16(d, pa, vh + 2 * t);
                    mma_f16(d, pa, vl + 2 * t);
                }
            }
        }

        __syncthreads();
        if (c + 2 < nc) load_kv(c + 2);
        cp_commit();
        if (c + 1 < nc) {
            asm volatile("cp.async.wait_group 1;" ::: "memory");
            __syncthreads();
        }
    }

    // ---- epilogue: normalize, bf16 hi/lo split, write Oh/Ol [M,D] ----
    const float inv0 = 1.0f / l0, inv1 = 1.0f / l1;
    const int qrow = qt * 128 + wid * 16 + g;
    const size_t row0 = (size_t)(b * L_ + qrow) * D_;
    const size_t row1 = row0 + (size_t)8 * D_;
#pragma unroll
    for (int nb = 0; nb < 8; nb++) {
        const int col = h * 64 + nb * 8 + t2;
        uint32_t ph, pl;
        pack_split(oacc[nb][0] * inv0, oacc[nb][1] * inv0, ph, pl);
        *reinterpret_cast<uint32_t*>(&g_Oh[row0 + col]) = ph;
        *reinterpret_cast<uint32_t*>(&g_Ol[row0 + col]) = pl;
        pack_split(oacc[nb][2] * inv1, oacc[nb][3] * inv1, ph, pl);
        *reinterpret_cast<uint32_t*>(&g_Oh[row1 + col]) = ph;
        *reinterpret_cast<uint32_t*>(&g_Ol[row1 + col]) = pl;
    }
}

// ---------------- launch ----------------
extern "C" void kernel_launch(void* const* d_in, const int* in_sizes, int n_in,
                              void* d_out, int out_size)
{
    const float* x     = (const float*)d_in[0];
    const float* w_qkv = (const float*)d_in[1];
    const float* b_qkv = (const float*)d_in[2];
    const float* w_out = (const float*)d_in[3];
    const float* b_out = (const float*)d_in[4];
    const void*  mask  = d_in[5];

    __nv_bfloat16 *Xh, *Xl, *Wqh, *Wql, *Woh, *Wol, *Oh, *Ol;
    cudaGetSymbolAddress((void**)&Xh,  g_Xh);
    cudaGetSymbolAddress((void**)&Xl,  g_Xl);
    cudaGetSymbolAddress((void**)&Wqh, g_Wqh);
    cudaGetSymbolAddress((void**)&Wql, g_Wql);
    cudaGetSymbolAddress((void**)&Woh, g_Woh);
    cudaGetSymbolAddress((void**)&Wol, g_Wol);
    cudaGetSymbolAddress((void**)&Oh,  g_Oh);
    cudaGetSymbolAddress((void**)&Ol,  g_Ol);

    cudaFuncSetAttribute(gemm_mma, cudaFuncAttributeMaxDynamicSharedMemorySize, GEMM_SMEM);
    cudaFuncSetAttribute(attn_mma, cudaFuncAttributeMaxDynamicSharedMemorySize, AT_SMEM);

    k_reset<<<1, 32>>>();
    k_detect<<<4, 256>>>((const unsigned int*)mask, (B_ * L_) / 4);
    k_conv<<<(B_ * L_ + 255) / 256, 256>>>(mask, B_ * L_);

    // operand prep
    k_split<<<(M_ * K_ / 4 + 255) / 256, 256>>>(x, Xh, Xl, M_ * K_ / 4);
    k_splitT<<<dim3(3 * D_ / 32, K_ / 32), dim3(32, 8)>>>(w_qkv, Wqh, Wql, 3 * D_);
    k_splitT<<<dim3(D_ / 32, K_ / 32), dim3(32, 8)>>>(w_out, Woh, Wol, D_);

    // QKV projection -> fp16 Q (single) + fp16 hi/lo K,V in [B,H,L,DH]
    gemm_mma<<<dim3(3 * D_ / 128, M_ / 128), 256, GEMM_SMEM>>>(
        Xh, Xl, Wqh, Wql, b_qkv, nullptr, 3 * D_, 1);

    // flash attention (fp16 tensor cores, masked-chunk skip)
    attn_mma<<<dim3(L_ / 128, H_, B_), 256, AT_SMEM>>>();

    // output projection (bf16 3-way)
    gemm_mma<<<dim3(D_ / 128, M_ / 128), 256, GEMM_SMEM>>>(
        Oh, Ol, Woh, Wol, b_out, (float*)d_out, D_, 0);
}